// round 2
// baseline (speedup 1.0000x reference)
#include <cuda_runtime.h>
#include <cuda_bf16.h>
#include <cstdint>

// out shape: (B=8, C=256, H=128, W=128) fp32. Output is independent of input x
// and identical across batches:
//   out[b,c,i,j] = c<128 ? trig_c(i) : trig_{c-128}(j)
//   trig_cc(p)   = (cc even ? sin : cos)(p * 10000^(-floor(cc/2)/128))
//
// Strategy: one block per (channel, plane-half). Build the 32KB half-plane in
// shared memory ONCE, then TMA-bulk-store it to all 8 batch locations.
// This rides the LTS cap instead of the per-thread STG path.

__global__ __launch_bounds__(256) void pe2d_tma_kernel(float* __restrict__ out) {
    __shared__ __align__(128) float plane[8192];   // 32 KB half-plane image
    __shared__ float s[128];                       // unique per-position values

    const int blk   = blockIdx.x;   // 0..511
    const int c     = blk >> 1;     // channel 0..255
    const int halfp = blk & 1;      // which 64 rows of the 128x128 plane
    const int tid   = threadIdx.x;

    if (tid < 128) {
        const int cc    = c & 127;          // channel within half
        const int pairk = cc >> 1;          // floor(cc/2)
        const float LOG2_10000 = 13.28771237954945f;
        float inv_dim = exp2f(-(float)pairk * (LOG2_10000 / 128.0f));
        float arg = (float)tid * inv_dim;   // tid = position (i or j)
        float sv, cv;
        sincosf(arg, &sv, &cv);
        s[tid] = (cc & 1) ? cv : sv;
    }
    __syncthreads();

    // Fill the half-plane: rows [halfp*64, halfp*64+64), 128 cols, as float4.
    // 2048 float4 / 256 threads = 8 STS.128 per thread, fully conflict-free.
    float4*       p4 = reinterpret_cast<float4*>(plane);
    const float4* s4 = reinterpret_cast<const float4*>(s);
    const bool lower = (c < 128);
    #pragma unroll
    for (int t = 0; t < 8; t++) {
        const int idx4 = tid + t * 256;               // 0..2047
        float4 v;
        if (lower) {
            // constant along j: broadcast s[row]
            const int row = (idx4 >> 5) + halfp * 64; // 32 float4 per row
            const float x = s[row];                   // warp-uniform smem broadcast
            v = make_float4(x, x, x, x);
        } else {
            // constant along i: every row is s[0..127]
            v = s4[idx4 & 31];
        }
        p4[idx4] = v;
    }
    __syncthreads();

    // Order the generic-proxy smem writes before the async-proxy TMA reads.
    asm volatile("fence.proxy.async.shared::cta;" ::: "memory");

    if (tid == 0) {
        uint32_t smem_addr = (uint32_t)__cvta_generic_to_shared(plane);
        // 8 batch copies of the same 32KB image (output is batch-invariant).
        #pragma unroll
        for (int b = 0; b < 8; b++) {
            float* dst = out + (((size_t)b * 256 + (size_t)c) * 16384)
                             + (size_t)halfp * 8192;
            asm volatile(
                "cp.async.bulk.global.shared::cta.bulk_group [%0], [%1], %2;"
                :: "l"(dst), "r"(smem_addr), "n"(32768) : "memory");
        }
        asm volatile("cp.async.bulk.commit_group;" ::: "memory");
        // Must not let the CTA retire (and smem be reassigned) while the TMA
        // engine is still reading the image: wait for the smem READS to drain.
        asm volatile("cp.async.bulk.wait_group.read 0;" ::: "memory");
    }
    // Block completes only when thread 0's wait finishes -> smem stays valid.
}

extern "C" void kernel_launch(void* const* d_in, const int* in_sizes, int n_in,
                              void* d_out, int out_size) {
    (void)d_in; (void)in_sizes; (void)n_in; (void)out_size;
    // 256 channels x 2 plane-halves
    pe2d_tma_kernel<<<512, 256>>>((float*)d_out);
}

// round 3
// speedup vs baseline: 1.1892x; 1.1892x over previous
#include <cuda_runtime.h>
#include <cuda_bf16.h>

// out shape: (B=8, C=256, H=128, W=128) fp32, row-major. Output is independent
// of the input tensor and identical across batches:
//   out[b,c,i,j] = c<128 ? trig_c(i) : trig_{c-128}(j)
//   trig_cc(p)   = (cc even ? sin : cos)(p * 10000^(-floor(cc/2)/128))
//
// The kernel is pure write-bandwidth bound at the LTS (L2) write cap
// (~6300 B/cyc chip-wide). Strategy: one block per (b,c) plane, 128 unique
// values in smem, then a maximally dense burst of streaming float4 stores.

__global__ __launch_bounds__(256) void pe2d_kernel(float* __restrict__ out) {
    const int bc  = blockIdx.x;       // b*256 + c
    const int c   = bc & 255;
    const int tid = threadIdx.x;

    __shared__ float s[128];

    if (tid < 128) {
        const int cc    = c & 127;        // channel within half
        const int pairk = cc >> 1;        // floor(cc/2)
        const float LOG2_10000 = 13.28771237954945f;
        float inv_dim = exp2f(-(float)pairk * (LOG2_10000 / 128.0f));
        float arg = (float)tid * inv_dim; // tid = position (i or j)
        float sv, cv;
        sincosf(arg, &sv, &cv);
        s[tid] = (cc & 1) ? cv : sv;
    }
    __syncthreads();

    // Per-thread: 16 float4 stores, consecutive lanes -> consecutive float4
    // (512B per warp per store, fully coalesced). Stage all values in
    // registers FIRST, then burst the 16 streaming stores back-to-back so the
    // LSU/L2 queue stays saturated with no interleaved LDS or index math.
    float4 v[16];
    if (c < 128) {
        // value constant along j: row index = idx4 >> 5
        #pragma unroll
        for (int t = 0; t < 16; t++) {
            const int row = (tid + t * 256) >> 5;   // warp-uniform
            const float x = s[row];                 // smem broadcast
            v[t] = make_float4(x, x, x, x);
        }
    } else {
        // value varies along j only: every row replicates s[0..127]
        const float4* s4 = reinterpret_cast<const float4*>(s);
        #pragma unroll
        for (int t = 0; t < 16; t++) {
            v[t] = s4[(tid + t * 256) & 31];        // conflict-free LDS.128
        }
    }

    float4* outp = reinterpret_cast<float4*>(out) + (size_t)bc * 4096 + tid;
    #pragma unroll
    for (int t = 0; t < 16; t++) {
        __stcs(outp + t * 256, v[t]);               // st.global.cs.v4 (evict-first)
    }
}

extern "C" void kernel_launch(void* const* d_in, const int* in_sizes, int n_in,
                              void* d_out, int out_size) {
    (void)d_in; (void)in_sizes; (void)n_in; (void)out_size;
    // 8 batches * 256 channels = 2048 planes
    pe2d_kernel<<<2048, 256>>>((float*)d_out);
}